// round 16
// baseline (speedup 1.0000x reference)
#include <cuda_runtime.h>
#include <math.h>

#define TOKENS     8192
#define MODEL_DIM  4096
#define PROMPT_DIM 64
#define KTOT       (MODEL_DIM + PROMPT_DIM)   // 4160
#define NE         8
#define NP         4                          // expert pairs
#define TPW        4                          // tokens per warp
#define WARPS      16
#define TPB        (TPW * WARPS)              // 64 tokens per block
#define THREADS    512
#define GRID       (TOKENS / TPB)             // 128 CTAs, one wave
#define DSTRIDE    4162                       // per-pair row, float2 units
#define SMEM_BYTES (NP * DSTRIDE * 8)         // 133,184 B
#define CHUNK      128                        // dims per K-chunk (float4/lane = 512B burst)
#define NIT        (MODEL_DIM / CHUNK)        // 32
#define RING       3                          // prefetch distance 2

// d = a*b + d elementwise on packed fp32x2
__device__ __forceinline__ void ffma2(unsigned long long& d,
                                      unsigned long long a,
                                      unsigned long long b) {
    asm("fma.rn.f32x2 %0, %1, %2, %0;" : "+l"(d) : "l"(a), "l"(b));
}
__device__ __forceinline__ unsigned long long dup2(float v) {
    unsigned long long r;
    asm("mov.b64 %0, {%1, %1};" : "=l"(r) : "f"(v));
    return r;
}
__device__ __forceinline__ void unpack2(unsigned long long v, float& lo, float& hi) {
    asm("mov.b64 {%0, %1}, %2;" : "=f"(lo), "=f"(hi) : "l"(v));
}
__device__ __forceinline__ void l2_prefetch(const void* g, unsigned bytes) {
    asm volatile("cp.async.bulk.prefetch.L2.global [%0], %1;" :: "l"(g), "r"(bytes));
}

__global__ __launch_bounds__(THREADS, 1)
void topkgate_kernel(const float* __restrict__ x,
                     const float* __restrict__ prompt,
                     const float* __restrict__ W,
                     const float* __restrict__ b,
                     float* __restrict__ out)
{
    extern __shared__ float2 wsp[];   // wsp[p * DSTRIDE + d] = (W[d][2p], W[d][2p+1])

    const int tid   = threadIdx.x;
    const int w     = tid >> 5;
    const int lane  = tid & 31;
    const int tbase = blockIdx.x * TPB + w * TPW;   // grid covers TOKENS exactly

    // x base for this warp's 4 tokens (per-token offsets are immediates)
    const float* xb = x + (size_t)tbase * MODEL_DIM + 4 * lane;

    // ---- L2 warm-start: engine pulls first 8 KB of each token row into L2
    //      while we stage W below ----
    if (lane == 0) {
#pragma unroll
        for (int m = 0; m < TPW; m++)
            l2_prefetch(x + (size_t)(tbase + m) * MODEL_DIM, 8192);
    }

    // ---- Ring prologue: chunks 0,1 in flight before W staging ----
    float4 buf[RING][TPW];
#pragma unroll
    for (int q = 0; q < RING - 1; q++)
#pragma unroll
        for (int m = 0; m < TPW; m++)
            buf[q][m] = __ldcs((const float4*)(xb + m * MODEL_DIM + q * CHUNK));

    // ---- Stage W into expert-paired SMEM layout via LDG.128 ----
    // ulonglong2 i = row d = i>>1, pairs {2h, 2h+1} where h = i&1.
    {
        const ulonglong2* Wv2 = (const ulonglong2*)W;
        for (int i = tid; i < KTOT * 2; i += THREADS) {
            const int d = i >> 1;
            const int h = i & 1;
            const ulonglong2 v = Wv2[i];
            *(unsigned long long*)&wsp[(2 * h)     * DSTRIDE + d] = v.x;
            *(unsigned long long*)&wsp[(2 * h + 1) * DSTRIDE + d] = v.y;
        }
    }
    __syncthreads();

    // Packed accumulators: acc[m][p] = (logit[2p], logit[2p+1]) partial sums
    unsigned long long acc[TPW][NP];
#pragma unroll
    for (int m = 0; m < TPW; m++)
#pragma unroll
        for (int p = 0; p < NP; p++) acc[m][p] = 0ull;

    // ---- Mainloop: 3-deep register ring, prefetch distance 2 ----
    for (int it = 0; it < NIT; it += RING) {
#pragma unroll
        for (int u = 0; u < RING; u++) {
            const int j = it + u;
            if (j < NIT) {
                // Prefetch chunk j+2 into ring slot (u+2)%3
                if (j + (RING - 1) < NIT) {
                    const int slot = (u + RING - 1) % RING;
#pragma unroll
                    for (int m = 0; m < TPW; m++)
                        buf[slot][m] = __ldcs(
                            (const float4*)(xb + m * MODEL_DIM + (j + RING - 1) * CHUNK));
                }

                // W slice: dims d0..d0+3 for 4 expert pairs — 8x LDS.128, conflict-free
                const int d0 = j * CHUNK + 4 * lane;
                ulonglong2 wv[NP][2];
#pragma unroll
                for (int p = 0; p < NP; p++) {
                    wv[p][0] = *(const ulonglong2*)&wsp[p * DSTRIDE + d0];      // dims d0, d0+1
                    wv[p][1] = *(const ulonglong2*)&wsp[p * DSTRIDE + d0 + 2];  // dims d0+2, d0+3
                }

#pragma unroll
                for (int m = 0; m < TPW; m++) {
                    const float4 xv = buf[u][m];
                    const unsigned long long x0 = dup2(xv.x);
                    const unsigned long long x1 = dup2(xv.y);
                    const unsigned long long x2 = dup2(xv.z);
                    const unsigned long long x3 = dup2(xv.w);
#pragma unroll
                    for (int p = 0; p < NP; p++) {
                        ffma2(acc[m][p], x0, wv[p][0].x);
                        ffma2(acc[m][p], x1, wv[p][0].y);
                        ffma2(acc[m][p], x2, wv[p][1].x);
                        ffma2(acc[m][p], x3, wv[p][1].y);
                    }
                }
            }
        }
    }

    // ---- Prompt tail: lane handles dims (4096+2*lane, +1) for all tokens ----
    {
        const int po = MODEL_DIM + 2 * lane;
        ulonglong2 wp[NP];
#pragma unroll
        for (int p = 0; p < NP; p++)
            wp[p] = *(const ulonglong2*)&wsp[p * DSTRIDE + po];
#pragma unroll
        for (int m = 0; m < TPW; m++) {
            const float2 pv = *(const float2*)(prompt + (size_t)(tbase + m) * PROMPT_DIM + 2 * lane);
            const unsigned long long plo = dup2(pv.x);
            const unsigned long long phi = dup2(pv.y);
#pragma unroll
            for (int p = 0; p < NP; p++) {
                ffma2(acc[m][p], plo, wp[p].x);
                ffma2(acc[m][p], phi, wp[p].y);
            }
        }
    }

    // ---- Unpack to scalar accumulators ----
    float accf[TPW][NE];
#pragma unroll
    for (int m = 0; m < TPW; m++)
#pragma unroll
        for (int p = 0; p < NP; p++)
            unpack2(acc[m][p], accf[m][2 * p], accf[m][2 * p + 1]);

    // ---- Warp butterfly reduction over lanes ----
#pragma unroll
    for (int off = 16; off > 0; off >>= 1) {
#pragma unroll
        for (int m = 0; m < TPW; m++)
#pragma unroll
            for (int e = 0; e < NE; e++)
                accf[m][e] += __shfl_xor_sync(0xffffffffu, accf[m][e], off);
    }

    // ---- Epilogue: lane m handles token (tbase + m) ----
    if (lane < TPW) {
        const int t = tbase + lane;

        float lg[NE];
#pragma unroll
        for (int m = 0; m < TPW; m++) {
            if (lane == m) {
#pragma unroll
                for (int e = 0; e < NE; e++) lg[e] = accf[m][e];
            }
        }
#pragma unroll
        for (int e = 0; e < NE; e++) lg[e] += b[e];

        // Top-2 with first-index tie-break (matches jax.lax.top_k)
        int i0 = 0; float m0 = lg[0];
#pragma unroll
        for (int e = 1; e < NE; e++)
            if (lg[e] > m0) { m0 = lg[e]; i0 = e; }
        int i1 = -1; float m1 = -INFINITY;
#pragma unroll
        for (int e = 0; e < NE; e++)
            if (e != i0 && lg[e] > m1) { m1 = lg[e]; i1 = e; }

        // Softmax over 8 (max-subtracted), gather top-2, renormalize with EPS clamp
        float s = 0.0f;
#pragma unroll
        for (int e = 0; e < NE; e++) s += __expf(lg[e] - m0);
        const float g0 = 1.0f / s;
        const float g1 = __expf(m1 - m0) / s;
        const float denom = fmaxf(g0 + g1, 1.1920929e-07f);
        const float r0 = g0 / denom;
        const float r1 = g1 / denom;

        // masks: [T, 2, 8] at offset 0
        float* mrow = out + (size_t)t * 16;
        const float4 z = make_float4(0.f, 0.f, 0.f, 0.f);
        *(float4*)(mrow + 0)  = z;
        *(float4*)(mrow + 4)  = z;
        *(float4*)(mrow + 8)  = z;
        *(float4*)(mrow + 12) = z;
        mrow[i0]     = 1.0f;
        mrow[8 + i1] = 1.0f;

        // gates_s: [T, 2] at offset T*16
        float* grow = out + (size_t)TOKENS * 16 + (size_t)t * 2;
        grow[0] = r0;
        grow[1] = r1;
    }
}

extern "C" void kernel_launch(void* const* d_in, const int* in_sizes, int n_in,
                              void* d_out, int out_size)
{
    const float* x      = (const float*)d_in[0];
    const float* prompt = (const float*)d_in[1];
    const float* W      = (const float*)d_in[2];
    const float* b      = (const float*)d_in[3];
    float* out          = (float*)d_out;

    cudaFuncSetAttribute(topkgate_kernel,
                         cudaFuncAttributeMaxDynamicSharedMemorySize, SMEM_BYTES);

    topkgate_kernel<<<GRID, THREADS, SMEM_BYTES>>>(x, prompt, W, b, out);
}

// round 17
// speedup vs baseline: 1.1452x; 1.1452x over previous
#include <cuda_runtime.h>
#include <math.h>

#define TOKENS     8192
#define MODEL_DIM  4096
#define PROMPT_DIM 64
#define KTOT       (MODEL_DIM + PROMPT_DIM)   // 4160
#define NE         8
#define NP         4                          // expert pairs
#define TPW        4                          // tokens per warp
#define WARPS      16
#define TPB        (TPW * WARPS)              // 64 tokens per block
#define THREADS    512
#define GRID       (TOKENS / TPB)             // 128 CTAs, one wave
#define DSTRIDE    4162                       // per-pair row, float2 units
#define SMEM_BYTES (NP * DSTRIDE * 8)         // 133,184 B
#define CHUNK      128                        // dims per K-chunk (float4/lane = 512B burst)
#define NIT        (MODEL_DIM / CHUNK)        // 32
#define RING       3                          // prefetch distance 2

// d = a*b + d elementwise on packed fp32x2
__device__ __forceinline__ void ffma2(unsigned long long& d,
                                      unsigned long long a,
                                      unsigned long long b) {
    asm("fma.rn.f32x2 %0, %1, %2, %0;" : "+l"(d) : "l"(a), "l"(b));
}
__device__ __forceinline__ unsigned long long dup2(float v) {
    unsigned long long r;
    asm("mov.b64 %0, {%1, %1};" : "=l"(r) : "f"(v));
    return r;
}
__device__ __forceinline__ void unpack2(unsigned long long v, float& lo, float& hi) {
    asm("mov.b64 {%0, %1}, %2;" : "=f"(lo), "=f"(hi) : "l"(v));
}

__global__ __launch_bounds__(THREADS, 1)
void topkgate_kernel(const float* __restrict__ x,
                     const float* __restrict__ prompt,
                     const float* __restrict__ W,
                     const float* __restrict__ b,
                     float* __restrict__ out)
{
    extern __shared__ float2 wsp[];   // wsp[p * DSTRIDE + d] = (W[d][2p], W[d][2p+1])

    const int tid   = threadIdx.x;
    const int w     = tid >> 5;
    const int lane  = tid & 31;
    const int tbase = blockIdx.x * TPB + w * TPW;   // grid covers TOKENS exactly

    // x base for this warp's 4 tokens (per-token offsets are immediates)
    const float* xb = x + (size_t)tbase * MODEL_DIM + 4 * lane;

    // ---- Ring prologue FIRST: x-load latency overlaps W staging below ----
    float4 buf[RING][TPW];
#pragma unroll
    for (int q = 0; q < RING - 1; q++)
#pragma unroll
        for (int m = 0; m < TPW; m++)
            buf[q][m] = __ldcs((const float4*)(xb + m * MODEL_DIM + q * CHUNK));

    // ---- Stage W into expert-paired SMEM layout (R13-proven pattern) ----
    {
        const float2* Wv = (const float2*)W;   // Wv[d*4 + p] = (W[d][2p], W[d][2p+1])
        for (int i = tid; i < KTOT * NP; i += THREADS) {
            int d = i >> 2;
            int p = i & 3;
            wsp[p * DSTRIDE + d] = Wv[i];
        }
    }
    __syncthreads();

    // Packed accumulators: acc[m][p] = (logit[2p], logit[2p+1]) partial sums
    unsigned long long acc[TPW][NP];
#pragma unroll
    for (int m = 0; m < TPW; m++)
#pragma unroll
        for (int p = 0; p < NP; p++) acc[m][p] = 0ull;

    // ---- Mainloop: 3-deep register ring, prefetch distance 2 ----
    for (int it = 0; it < NIT; it += RING) {
#pragma unroll
        for (int u = 0; u < RING; u++) {
            const int j = it + u;
            if (j < NIT) {
                // Prefetch chunk j+2 into ring slot (u+2)%3
                if (j + (RING - 1) < NIT) {
                    const int slot = (u + RING - 1) % RING;
#pragma unroll
                    for (int m = 0; m < TPW; m++)
                        buf[slot][m] = __ldcs(
                            (const float4*)(xb + m * MODEL_DIM + (j + RING - 1) * CHUNK));
                }

                // W slice: dims d0..d0+3 for 4 expert pairs — 8x LDS.128, conflict-free
                const int d0 = j * CHUNK + 4 * lane;
                ulonglong2 wv[NP][2];
#pragma unroll
                for (int p = 0; p < NP; p++) {
                    wv[p][0] = *(const ulonglong2*)&wsp[p * DSTRIDE + d0];      // dims d0, d0+1
                    wv[p][1] = *(const ulonglong2*)&wsp[p * DSTRIDE + d0 + 2];  // dims d0+2, d0+3
                }

#pragma unroll
                for (int m = 0; m < TPW; m++) {
                    const float4 xv = buf[u][m];
                    const unsigned long long x0 = dup2(xv.x);
                    const unsigned long long x1 = dup2(xv.y);
                    const unsigned long long x2 = dup2(xv.z);
                    const unsigned long long x3 = dup2(xv.w);
#pragma unroll
                    for (int p = 0; p < NP; p++) {
                        ffma2(acc[m][p], x0, wv[p][0].x);
                        ffma2(acc[m][p], x1, wv[p][0].y);
                        ffma2(acc[m][p], x2, wv[p][1].x);
                        ffma2(acc[m][p], x3, wv[p][1].y);
                    }
                }
            }
        }
    }

    // ---- Prompt tail: lane handles dims (4096+2*lane, +1) for all tokens ----
    {
        const int po = MODEL_DIM + 2 * lane;
        ulonglong2 wp[NP];
#pragma unroll
        for (int p = 0; p < NP; p++)
            wp[p] = *(const ulonglong2*)&wsp[p * DSTRIDE + po];
#pragma unroll
        for (int m = 0; m < TPW; m++) {
            const float2 pv = *(const float2*)(prompt + (size_t)(tbase + m) * PROMPT_DIM + 2 * lane);
            const unsigned long long plo = dup2(pv.x);
            const unsigned long long phi = dup2(pv.y);
#pragma unroll
            for (int p = 0; p < NP; p++) {
                ffma2(acc[m][p], plo, wp[p].x);
                ffma2(acc[m][p], phi, wp[p].y);
            }
        }
    }

    // ---- Unpack to scalar accumulators ----
    float accf[TPW][NE];
#pragma unroll
    for (int m = 0; m < TPW; m++)
#pragma unroll
        for (int p = 0; p < NP; p++)
            unpack2(acc[m][p], accf[m][2 * p], accf[m][2 * p + 1]);

    // ---- Warp butterfly reduction over lanes ----
#pragma unroll
    for (int off = 16; off > 0; off >>= 1) {
#pragma unroll
        for (int m = 0; m < TPW; m++)
#pragma unroll
            for (int e = 0; e < NE; e++)
                accf[m][e] += __shfl_xor_sync(0xffffffffu, accf[m][e], off);
    }

    // ---- Epilogue: lane m handles token (tbase + m) ----
    if (lane < TPW) {
        const int t = tbase + lane;

        float lg[NE];
#pragma unroll
        for (int m = 0; m < TPW; m++) {
            if (lane == m) {
#pragma unroll
                for (int e = 0; e < NE; e++) lg[e] = accf[m][e];
            }
        }
        // Bias via two vector loads (fewer tail LSU wavefronts than 8 scalars)
        {
            const float4 b0 = *(const float4*)(b + 0);
            const float4 b1 = *(const float4*)(b + 4);
            lg[0] += b0.x; lg[1] += b0.y; lg[2] += b0.z; lg[3] += b0.w;
            lg[4] += b1.x; lg[5] += b1.y; lg[6] += b1.z; lg[7] += b1.w;
        }

        // Top-2 with first-index tie-break (matches jax.lax.top_k)
        int i0 = 0; float m0 = lg[0];
#pragma unroll
        for (int e = 1; e < NE; e++)
            if (lg[e] > m0) { m0 = lg[e]; i0 = e; }
        int i1 = -1; float m1 = -INFINITY;
#pragma unroll
        for (int e = 0; e < NE; e++)
            if (e != i0 && lg[e] > m1) { m1 = lg[e]; i1 = e; }

        // Softmax over 8 (max-subtracted), gather top-2, renormalize with EPS clamp
        float s = 0.0f;
#pragma unroll
        for (int e = 0; e < NE; e++) s += __expf(lg[e] - m0);
        const float g0 = 1.0f / s;
        const float g1 = __expf(m1 - m0) / s;
        const float denom = fmaxf(g0 + g1, 1.1920929e-07f);
        const float r0 = g0 / denom;
        const float r1 = g1 / denom;

        // masks: [T, 2, 8] at offset 0
        float* mrow = out + (size_t)t * 16;
        const float4 z = make_float4(0.f, 0.f, 0.f, 0.f);
        *(float4*)(mrow + 0)  = z;
        *(float4*)(mrow + 4)  = z;
        *(float4*)(mrow + 8)  = z;
        *(float4*)(mrow + 12) = z;
        mrow[i0]     = 1.0f;
        mrow[8 + i1] = 1.0f;

        // gates_s: [T, 2] at offset T*16
        float* grow = out + (size_t)TOKENS * 16 + (size_t)t * 2;
        grow[0] = r0;
        grow[1] = r1;
    }
}

extern "C" void kernel_launch(void* const* d_in, const int* in_sizes, int n_in,
                              void* d_out, int out_size)
{
    const float* x      = (const float*)d_in[0];
    const float* prompt = (const float*)d_in[1];
    const float* W      = (const float*)d_in[2];
    const float* b      = (const float*)d_in[3];
    float* out          = (float*)d_out;

    cudaFuncSetAttribute(topkgate_kernel,
                         cudaFuncAttributeMaxDynamicSharedMemorySize, SMEM_BYTES);

    topkgate_kernel<<<GRID, THREADS, SMEM_BYTES>>>(x, prompt, W, b, out);
}